// round 11
// baseline (speedup 1.0000x reference)
#include <cuda_runtime.h>
#include <cuda_bf16.h>
#include <cstdint>

#define EMBED 2048
#define HD    128
#define NB    4
#define SEQ   2048

// ---------------------------------------------------------------------------
// Scratch globals
// ---------------------------------------------------------------------------
__device__ __align__(16) float g_Wt[3 * HD * EMBED];            // rna-tf32 [w][n][k] (row-major 384 x 2048)
__device__ __align__(16) __nv_bfloat16 g_qhi[NB * SEQ * HD];    // [b][s][d]
__device__ __align__(16) __nv_bfloat16 g_qlo[NB * SEQ * HD];
__device__ __align__(16) __nv_bfloat16 g_khi[NB * SEQ * HD];    // [b][s][d]
__device__ __align__(16) __nv_bfloat16 g_klo[NB * SEQ * HD];
__device__ __align__(16) __nv_bfloat16 g_vthi[NB * HD * SEQ];   // [b][d][s]
__device__ __align__(16) __nv_bfloat16 g_vtlo[NB * HD * SEQ];

__device__ __forceinline__ uint32_t pk2(__nv_bfloat16 a, __nv_bfloat16 b) {
    return ((uint32_t)__bfloat16_as_ushort(b) << 16) | __bfloat16_as_ushort(a);
}
__device__ __forceinline__ uint32_t smem_u32(const void* p) {
    uint32_t a;
    asm("{ .reg .u64 t; cvta.to.shared.u64 t, %1; cvt.u32.u64 %0, t; }"
        : "=r"(a) : "l"(p));
    return a;
}
__device__ __forceinline__ float tf32rna(float x) {
    uint32_t r;
    asm("cvt.rna.tf32.f32 %0, %1;" : "=r"(r) : "f"(x));
    return __uint_as_float(r);
}
// bf16 m16n8k16
__device__ __forceinline__ void mma16816(float* c, const uint32_t* a,
                                         const uint32_t* b) {
    asm volatile(
        "mma.sync.aligned.m16n8k16.row.col.f32.bf16.bf16.f32 "
        "{%0,%1,%2,%3}, {%4,%5,%6,%7}, {%8,%9}, {%0,%1,%2,%3};"
        : "+f"(c[0]), "+f"(c[1]), "+f"(c[2]), "+f"(c[3])
        : "r"(a[0]), "r"(a[1]), "r"(a[2]), "r"(a[3]), "r"(b[0]), "r"(b[1]));
}
// tf32 m16n8k8 (fragments via b16 ldmatrix on fp32 data; HW truncates to tf32)
__device__ __forceinline__ void mma1688t(float* c, const uint32_t* a,
                                         const uint32_t* b) {
    asm volatile(
        "mma.sync.aligned.m16n8k8.row.col.f32.tf32.tf32.f32 "
        "{%0,%1,%2,%3}, {%4,%5,%6,%7}, {%8,%9}, {%0,%1,%2,%3};"
        : "+f"(c[0]), "+f"(c[1]), "+f"(c[2]), "+f"(c[3])
        : "r"(a[0]), "r"(a[1]), "r"(a[2]), "r"(a[3]), "r"(b[0]), "r"(b[1]));
}
__device__ __forceinline__ void ldsm4(uint32_t* r, uint32_t saddr) {
    asm volatile("ldmatrix.sync.aligned.m8n8.x4.shared.b16 {%0,%1,%2,%3}, [%4];"
                 : "=r"(r[0]), "=r"(r[1]), "=r"(r[2]), "=r"(r[3]) : "r"(saddr));
}
__device__ __forceinline__ void cpa16(uint32_t dst, const void* src) {
    asm volatile("cp.async.cg.shared.global [%0], [%1], 16;"
                 :: "r"(dst), "l"(__cvta_generic_to_global(src)) : "memory");
}
#define CP_COMMIT() asm volatile("cp.async.commit_group;" ::: "memory")
#define CP_WAIT1()  asm volatile("cp.async.wait_group 1;" ::: "memory")

// ---------------------------------------------------------------------------
// prep_w48 (unchanged, passing): W fp32 [k][n] -> rna-tf32 fp32 [w][n][k]
// ---------------------------------------------------------------------------
__global__ __launch_bounds__(256)
void prep_w48(const float* __restrict__ Wq, const float* __restrict__ Wk,
              const float* __restrict__ Wv)
{
    __shared__ float Ws[128][132];
    const int t = threadIdx.x;
    const int w  = blockIdx.x >> 4;
    const int k0 = (blockIdx.x & 15) * 128;
    const float* __restrict__ W = (w == 0) ? Wq : (w == 1 ? Wk : Wv);

    for (int l = 0; l < 64; ++l) {
        int idx = t + l * 256;
        int kk = idx >> 7, n = idx & 127;
        Ws[kk][n] = W[(size_t)(k0 + kk) * HD + n];
    }
    __syncthreads();

    const int n = t >> 1, kh = (t & 1) * 64;
    float* dst = g_Wt + (size_t)w * HD * EMBED + (size_t)n * EMBED + k0 + kh;
    #pragma unroll
    for (int g = 0; g < 16; ++g) {
        float4 v = make_float4(tf32rna(Ws[kh + g * 4 + 0][n]),
                               tf32rna(Ws[kh + g * 4 + 1][n]),
                               tf32rna(Ws[kh + g * 4 + 2][n]),
                               tf32rna(Ws[kh + g * 4 + 3][n]));
        *(float4*)(dst + g * 4) = v;
    }
}

// ---------------------------------------------------------------------------
// qkv4: fused 3-in-1 TF32 GEMM. M64 x N384 x K2048, grid 128, 256 thr,
// 1 CTA/SM. Warp grid 1x8 (warp tile 64x48) -> B fragments read ONCE.
// A streamed from raw X; B from rna-tf32 g_Wt (row-major 384 x 2048).
// ---------------------------------------------------------------------------
#define KC    32
#define LDW   36
#define LDW16 72
#define A4STG (64 * LDW * 4)            // 9216
#define B4STG (384 * LDW * 4)           // 55296
#define O4_A  0
#define O4_B  (2 * A4STG)               // 18432
#define O4_BIAS (O4_B + 2 * B4STG)      // 129024
#define QSM4_TOTAL (O4_BIAS + 1536)     // 130560
#define CTS   396                       // epilogue Ct stride (floats)

__global__ __launch_bounds__(256)
void qkv4(const float* __restrict__ X,
          const float* __restrict__ bq, const float* __restrict__ bk,
          const float* __restrict__ bv)
{
    extern __shared__ char smem[];
    const uint32_t sb = smem_u32(smem);
    float* biasS = (float*)(smem + O4_BIAS);

    const int m0 = blockIdx.x * 64;
    const int t  = threadIdx.x;
    const int wn = t >> 5, lane = t & 31;
    const int g  = lane >> 2, tig = lane & 3;

    const int aiA = (((lane >> 3) & 1) * 8 + (lane & 7)) * LDW16 + (lane >> 4) * 8;
    const int biB = ((lane >> 4) * 8 + (lane & 7)) * LDW16 + ((lane >> 3) & 1) * 8;

    if (t < 128) { biasS[t] = bq[t]; biasS[128 + t] = bk[t]; biasS[256 + t] = bv[t]; }

    const int ar = t >> 2, ac = t & 3;      // A cp.async: row, 8-float chunk

    float c[4][6][4];
    #pragma unroll
    for (int i = 0; i < 4; ++i)
        #pragma unroll
        for (int j = 0; j < 6; ++j)
            #pragma unroll
            for (int q = 0; q < 4; ++q) c[i][j][q] = 0.f;

    // ---- prologue: stages 0,1
    #pragma unroll
    for (int pi = 0; pi < 2; ++pi) {
        const int kb = pi * KC;
        {
            const float* src = X + (size_t)(m0 + ar) * EMBED + kb + ac * 8;
            const uint32_t dst = sb + O4_A + pi * A4STG + ar * (LDW * 4) + ac * 32;
            cpa16(dst, src);
            cpa16(dst + 16, src + 4);
        }
        #pragma unroll
        for (int u = 0; u < 3; ++u) {
            const int unit = t + u * 256;          // 768 half-rows
            const int row = unit >> 1, half = unit & 1;
            const float* src = g_Wt + (size_t)row * EMBED + kb + half * 16;
            const uint32_t dst = sb + O4_B + pi * B4STG + row * (LDW * 4) + half * 64;
            #pragma unroll
            for (int j = 0; j < 4; ++j) cpa16(dst + j * 16, src + j * 4);
        }
        CP_COMMIT();
    }

    for (int kt = 0; kt < EMBED / KC; ++kt) {
        const int st = kt & 1;
        const uint32_t sA = sb + O4_A + st * A4STG;
        const uint32_t sB = sb + O4_B + st * B4STG;

        CP_WAIT1();
        __syncthreads();

        #pragma unroll
        for (int ks = 0; ks < 4; ++ks) {
            const int ko = ks * 16;
            uint32_t a[4][4], bb[3][4];
            #pragma unroll
            for (int mi = 0; mi < 4; ++mi)
                ldsm4(a[mi], sA + 2 * ((mi * 16) * LDW16 + ko + aiA));
            #pragma unroll
            for (int h = 0; h < 3; ++h)
                ldsm4(bb[h], sB + 2 * ((wn * 48 + h * 16) * LDW16 + ko + biB));
            #pragma unroll
            for (int mi = 0; mi < 4; ++mi)
                #pragma unroll
                for (int nt = 0; nt < 6; ++nt)
                    mma1688t(c[mi][nt], a[mi], &bb[nt >> 1][(nt & 1) * 2]);
        }
        __syncthreads();

        if (kt + 2 < EMBED / KC) {
            const int kb = (kt + 2) * KC;
            {
                const float* src = X + (size_t)(m0 + ar) * EMBED + kb + ac * 8;
                const uint32_t dst = sb + O4_A + st * A4STG + ar * (LDW * 4) + ac * 32;
                cpa16(dst, src);
                cpa16(dst + 16, src + 4);
            }
            #pragma unroll
            for (int u = 0; u < 3; ++u) {
                const int unit = t + u * 256;
                const int row = unit >> 1, half = unit & 1;
                const float* src = g_Wt + (size_t)row * EMBED + kb + half * 16;
                const uint32_t dst = sb + O4_B + st * B4STG + row * (LDW * 4) + half * 64;
                #pragma unroll
                for (int j = 0; j < 4; ++j) cpa16(dst + j * 16, src + j * 4);
            }
        }
        CP_COMMIT();
    }

    // ---- epilogue: frags (+bias) -> Ct[64][CTS] -> bf16 hi/lo gmem
    __syncthreads();
    float (*Ct)[CTS] = (float (*)[CTS])smem;
    #pragma unroll
    for (int mi = 0; mi < 4; ++mi) {
        const int r = mi * 16 + g;
        #pragma unroll
        for (int nt = 0; nt < 6; ++nt) {
            const int n = wn * 48 + nt * 8 + tig * 2;
            Ct[r][n]         = c[mi][nt][0] + biasS[n];
            Ct[r][n + 1]     = c[mi][nt][1] + biasS[n + 1];
            Ct[r + 8][n]     = c[mi][nt][2] + biasS[n];
            Ct[r + 8][n + 1] = c[mi][nt][3] + biasS[n + 1];
        }
    }
    __syncthreads();

    const int batch = m0 >> 11, s0 = m0 & 2047;
    // q (w=0) and k (w=1): [b][s][d] bf16 hi/lo
    #pragma unroll
    for (int w = 0; w < 2; ++w) {
        const int r = t >> 2, dq = (t & 3) * 32;
        __nv_bfloat16* dhi = (w == 0 ? g_qhi : g_khi)
            + ((size_t)batch * SEQ + s0 + r) * HD + dq;
        __nv_bfloat16* dlo = (w == 0 ? g_qlo : g_klo)
            + ((size_t)batch * SEQ + s0 + r) * HD + dq;
        #pragma unroll
        for (int qq = 0; qq < 4; ++qq) {
            uint32_t hp[4], lp[4];
            #pragma unroll
            for (int e = 0; e < 4; ++e) {
                float x0 = Ct[r][w * 128 + dq + qq * 8 + e * 2];
                float x1 = Ct[r][w * 128 + dq + qq * 8 + e * 2 + 1];
                __nv_bfloat16 h0 = __float2bfloat16(x0);
                __nv_bfloat16 h1 = __float2bfloat16(x1);
                hp[e] = pk2(h0, h1);
                lp[e] = pk2(__float2bfloat16(x0 - __bfloat162float(h0)),
                            __float2bfloat16(x1 - __bfloat162float(h1)));
            }
            *(uint4*)(dhi + qq * 8) = make_uint4(hp[0], hp[1], hp[2], hp[3]);
            *(uint4*)(dlo + qq * 8) = make_uint4(lp[0], lp[1], lp[2], lp[3]);
        }
    }
    // v (w=2): transposed [b][d][s] bf16 hi/lo
    {
        const int d = t >> 1, sch = (t & 1) * 32;
        size_t base = ((size_t)batch * HD + d) * SEQ + s0 + sch;
        #pragma unroll
        for (int qq = 0; qq < 4; ++qq) {
            uint32_t hp[4], lp[4];
            #pragma unroll
            for (int e = 0; e < 4; ++e) {
                float x0 = Ct[sch + qq * 8 + e * 2][256 + d];
                float x1 = Ct[sch + qq * 8 + e * 2 + 1][256 + d];
                __nv_bfloat16 h0 = __float2bfloat16(x0);
                __nv_bfloat16 h1 = __float2bfloat16(x1);
                hp[e] = pk2(h0, h1);
                lp[e] = pk2(__float2bfloat16(x0 - __bfloat162float(h0)),
                            __float2bfloat16(x1 - __bfloat162float(h1)));
            }
            *(uint4*)(g_vthi + base + qq * 8) = make_uint4(hp[0], hp[1], hp[2], hp[3]);
            *(uint4*)(g_vtlo + base + qq * 8) = make_uint4(lp[0], lp[1], lp[2], lp[3]);
        }
    }
}

// ---------------------------------------------------------------------------
// Attention v4 (unchanged, passing): bf16 3-term, cp.async 2-stage pipeline,
// 64-wide k-subtiles, balanced causal pairing. grid (32, 4).
// ---------------------------------------------------------------------------
#define KT   64
#define LDK  136
#define LDV  72
#define LDP  72
#define SPS  68

#define AO_QHI  0
#define AO_QLO  (AO_QHI + 32 * LDK * 2)
#define AO_KHI  (AO_QLO + 32 * LDK * 2)
#define AO_KLO  (AO_KHI + 2 * KT * LDK * 2)
#define AO_VHI  (AO_KLO + 2 * KT * LDK * 2)
#define AO_VLO  (AO_VHI + 2 * HD * LDV * 2)
#define AO_PS   (AO_VLO + 2 * HD * LDV * 2)
#define AO_PB   (AO_PS  + 32 * SPS * 4)
#define AO_PBL  (AO_PB  + 32 * LDP * 2)
#define AO_MLA  (AO_PBL + 32 * LDP * 2)
#define ASM_TOTAL (AO_MLA + 3 * 32 * 4)

__global__ __launch_bounds__(256)
void attn4(float* __restrict__ out)
{
    extern __shared__ char smem[];
    const uint32_t sb = smem_u32(smem);
    float* Ps   = (float*)(smem + AO_PS);
    float* m_s  = (float*)(smem + AO_MLA);
    float* l_s  = m_s + 32;
    float* al_s = l_s + 32;

    const int b = blockIdx.y, t = threadIdx.x;
    const int wid = t >> 5, lane = t & 31;
    const int g = lane >> 2, tig = lane & 3;
    const int wm = wid & 1, wn = wid >> 1;

    const int aiQ = (((lane >> 3) & 1) * 8 + (lane & 7)) * LDK + (lane >> 4) * 8;
    const int biK = ((lane >> 4) * 8 + (lane & 7)) * LDK + ((lane >> 3) & 1) * 8;
    const int aiP = (((lane >> 3) & 1) * 8 + (lane & 7)) * LDP + (lane >> 4) * 8;
    const int biV = ((lane >> 4) * 8 + (lane & 7)) * LDV + ((lane >> 3) & 1) * 8;

    const __nv_bfloat16* gQh = g_qhi + (size_t)b * SEQ * HD;
    const __nv_bfloat16* gQl = g_qlo + (size_t)b * SEQ * HD;
    const __nv_bfloat16* gKh = g_khi + (size_t)b * SEQ * HD;
    const __nv_bfloat16* gKl = g_klo + (size_t)b * SEQ * HD;
    const __nv_bfloat16* gVh = g_vthi + (size_t)b * HD * SEQ;
    const __nv_bfloat16* gVl = g_vtlo + (size_t)b * HD * SEQ;

    const float RSC = 0.08838834764831845f;
    const int sr = t >> 3, sc0 = (t & 7) * 8;
    const int kr = t >> 2, kq = t & 3;
    const int vr = t >> 1, vhh = t & 1;

    for (int subt = 0; subt < 2; ++subt) {
        const int jt = subt ? (63 - blockIdx.x) : blockIdx.x;
        const int q0 = jt * 32;
        const int iters = (jt >> 1) + 1;

        {
            const int r = t >> 3, dq = (t & 7) * 16;
            const __nv_bfloat16* sh = gQh + (size_t)(q0 + r) * HD + dq;
            const __nv_bfloat16* sl = gQl + (size_t)(q0 + r) * HD + dq;
            *(uint4*)(smem + AO_QHI + (r * LDK + dq) * 2)      = *(const uint4*)sh;
            *(uint4*)(smem + AO_QHI + (r * LDK + dq + 8) * 2)  = *(const uint4*)(sh + 8);
            *(uint4*)(smem + AO_QLO + (r * LDK + dq) * 2)      = *(const uint4*)sl;
            *(uint4*)(smem + AO_QLO + (r * LDK + dq + 8) * 2)  = *(const uint4*)(sl + 8);
        }
        if (t < 32) { m_s[t] = -1e30f; l_s[t] = 0.f; }

        float o[4][4];
        #pragma unroll
        for (int nt = 0; nt < 4; ++nt)
            #pragma unroll
            for (int q = 0; q < 4; ++q) o[nt][q] = 0.f;

        #pragma unroll
        for (int pi = 0; pi < 2; ++pi) {
            if (pi < iters) {
                const int k0 = pi * KT;
                const uint32_t kh_d = sb + AO_KHI + pi * (KT * LDK * 2) + kr * (LDK * 2) + kq * 64;
                const uint32_t kl_d = sb + AO_KLO + pi * (KT * LDK * 2) + kr * (LDK * 2) + kq * 64;
                const uint32_t vh_d = sb + AO_VHI + pi * (HD * LDV * 2) + vr * (LDV * 2) + vhh * 64;
                const uint32_t vl_d = sb + AO_VLO + pi * (HD * LDV * 2) + vr * (LDV * 2) + vhh * 64;
                const __nv_bfloat16* ksh = gKh + (size_t)(k0 + kr) * HD + kq * 32;
                const __nv_bfloat16* ksl = gKl + (size_t)(k0 + kr) * HD + kq * 32;
                const __nv_bfloat16* vsh = gVh + (size_t)vr * SEQ + k0 + vhh * 32;
                const __nv_bfloat16* vsl = gVl + (size_t)vr * SEQ + k0 + vhh * 32;
                #pragma unroll
                for (int j = 0; j < 4; ++j) {
                    cpa16(kh_d + j * 16, ksh + j * 8);
                    cpa16(kl_d + j * 16, ksl + j * 8);
                    cpa16(vh_d + j * 16, vsh + j * 8);
                    cpa16(vl_d + j * 16, vsl + j * 8);
                }
            }
            CP_COMMIT();
        }

        for (int it = 0; it < iters; ++it) {
            const int k0 = it * KT;
            const int st = it & 1;
            const uint32_t sKhi = sb + AO_KHI + st * (KT * LDK * 2);
            const uint32_t sKlo = sb + AO_KLO + st * (KT * LDK * 2);
            const uint32_t sVhi = sb + AO_VHI + st * (HD * LDV * 2);
            const uint32_t sVlo = sb + AO_VLO + st * (HD * LDV * 2);

            CP_WAIT1();
            __syncthreads();

            float s4[2][4];
            #pragma unroll
            for (int nt = 0; nt < 2; ++nt)
                #pragma unroll
                for (int q = 0; q < 4; ++q) s4[nt][q] = 0.f;
            #pragma unroll
            for (int ks = 0; ks < 8; ++ks) {
                const int k0s = ks * 16;
                uint32_t qh[4], ql[4], kh[4], kl[4];
                const uint32_t ao = 2 * (wm * 16 * LDK + k0s + aiQ);
                ldsm4(qh, sb + AO_QHI + ao);
                ldsm4(ql, sb + AO_QLO + ao);
                const uint32_t bo = 2 * (wn * 16 * LDK + k0s + biK);
                ldsm4(kh, sKhi + bo);
                ldsm4(kl, sKlo + bo);
                #pragma unroll
                for (int nt = 0; nt < 2; ++nt) {
                    mma16816(s4[nt], qh, &kh[nt * 2]);
                    mma16816(s4[nt], qh, &kl[nt * 2]);
                    mma16816(s4[nt], ql, &kh[nt * 2]);
                }
            }
            {
                const int row0 = wm * 16 + g;
                #pragma unroll
                for (int nt = 0; nt < 2; ++nt) {
                    const int col = wn * 16 + nt * 8 + tig * 2;
                    *(float2*)&Ps[row0 * SPS + col] = make_float2(s4[nt][0], s4[nt][1]);
                    *(float2*)&Ps[(row0 + 8) * SPS + col] = make_float2(s4[nt][2], s4[nt][3]);
                }
            }
            __syncthreads();

            {
                const int gq = q0 + sr;
                float sv[8];
                float rm = -1e30f;
                #pragma unroll
                for (int j = 0; j < 8; ++j) {
                    float v = Ps[sr * SPS + sc0 + j] * RSC;
                    if (k0 + sc0 + j > gq) v = -1e10f;
                    sv[j] = v;
                    rm = fmaxf(rm, v);
                }
                #pragma unroll
                for (int off = 4; off >= 1; off >>= 1)
                    rm = fmaxf(rm, __shfl_xor_sync(0xffffffffu, rm, off));
                const float mo = m_s[sr];
                const float mn = fmaxf(mo, rm);
                float rs = 0.f;
                uint32_t pph[4], ppl[4];
                #pragma unroll
                for (int j = 0; j < 4; ++j) {
                    float p0 = __expf(sv[2 * j] - mn);
                    float p1 = __expf(sv[2 * j + 1] - mn);
                    rs += p0 + p1;
                    __nv_bfloat16 h0 = __float2bfloat16(p0);
                    __nv_bfloat16 h1 = __float2bfloat16(p1);
                    pph[j] = pk2(h0, h1);
                    ppl[j] = pk2(__float2bfloat16(p0 - __bfloat162float(h0)),
                                 __float2bfloat16(p1 - __bfloat162float(h1)));
                }
                #pragma unroll
                for (int off = 4; off >= 1; off >>= 1)
                    rs += __shfl_xor_sync(0xffffffffu, rs, off);
                *(uint4*)(smem + AO_PB  + (sr * LDP + sc0) * 2) =
                    make_uint4(pph[0], pph[1], pph[2], pph[3]);
                *(uint4*)(smem + AO_PBL + (sr * LDP + sc0) * 2) =
                    make_uint4(ppl[0], ppl[1], ppl[2], ppl[3]);
                if ((t & 7) == 0) {
                    const float al = __expf(mo - mn);
                    m_s[sr]  = mn;
                    al_s[sr] = al;
                    l_s[sr]  = l_s[sr] * al + rs;
                }
            }
            __syncthreads();

            {
                const float a0 = al_s[wm * 16 + g];
                const float a1 = al_s[wm * 16 + g + 8];
                #pragma unroll
                for (int nt = 0; nt < 4; ++nt) {
                    o[nt][0] *= a0; o[nt][1] *= a0;
                    o[nt][2] *= a1; o[nt][3] *= a1;
                }
                #pragma unroll
                for (int ks = 0; ks < 4; ++ks) {
                    const int k0s = ks * 16;
                    uint32_t pa[4], pal[4], vh[2][4], vl[2][4];
                    const uint32_t po = 2 * (wm * 16 * LDP + k0s + aiP);
                    ldsm4(pa,  sb + AO_PB  + po);
                    ldsm4(pal, sb + AO_PBL + po);
                    #pragma unroll
                    for (int h = 0; h < 2; ++h) {
                        const uint32_t bo = 2 * ((wn * 32 + h * 16) * LDV + k0s + biV);
                        ldsm4(vh[h], sVhi + bo);
                        ldsm4(vl[h], sVlo + bo);
                    }
                    #pragma unroll
                    for (int nt = 0; nt < 4; ++nt) {
                        const uint32_t* vhp = &vh[nt >> 1][(nt & 1) * 2];
                        const uint32_t* vlp = &vl[nt >> 1][(nt & 1) * 2];
                        mma16816(o[nt], pa,  vhp);
                        mma16816(o[nt], pa,  vlp);
                        mma16816(o[nt], pal, vhp);
                    }
                }
            }
            __syncthreads();

            if (it + 2 < iters) {
                const int kn = (it + 2) * KT;
                const uint32_t kh_d = sb + AO_KHI + st * (KT * LDK * 2) + kr * (LDK * 2) + kq * 64;
                const uint32_t kl_d = sb + AO_KLO + st * (KT * LDK * 2) + kr * (LDK * 2) + kq * 64;
                const uint32_t vh_d = sb + AO_VHI + st * (HD * LDV * 2) + vr * (LDV * 2) + vhh * 64;
                const uint32_t vl_d = sb + AO_VLO + st * (HD * LDV * 2) + vr * (LDV * 2) + vhh * 64;
                const __nv_bfloat16* ksh = gKh + (size_t)(kn + kr) * HD + kq * 32;
                const __nv_bfloat16* ksl = gKl + (size_t)(kn + kr) * HD + kq * 32;
                const __nv_bfloat16* vsh = gVh + (size_t)vr * SEQ + kn + vhh * 32;
                const __nv_bfloat16* vsl = gVl + (size_t)vr * SEQ + kn + vhh * 32;
                #pragma unroll
                for (int j = 0; j < 4; ++j) {
                    cpa16(kh_d + j * 16, ksh + j * 8);
                    cpa16(kl_d + j * 16, ksl + j * 8);
                    cpa16(vh_d + j * 16, vsh + j * 8);
                    cpa16(vl_d + j * 16, vsl + j * 8);
                }
            }
            CP_COMMIT();
        }

        {
            const float li0 = 1.f / l_s[wm * 16 + g];
            const float li1 = 1.f / l_s[wm * 16 + g + 8];
            float* op0 = out + ((size_t)b * SEQ + q0 + wm * 16 + g) * HD;
            float* op1 = op0 + 8 * HD;
            #pragma unroll
            for (int nt = 0; nt < 4; ++nt) {
                const int d = wn * 32 + nt * 8 + tig * 2;
                *(float2*)(op0 + d) = make_float2(o[nt][0] * li0, o[nt][1] * li0);
                *(float2*)(op1 + d) = make_float2(o[nt][2] * li1, o[nt][3] * li1);
            }
        }
        __syncthreads();
    }
}

// ---------------------------------------------------------------------------
extern "C" void kernel_launch(void* const* d_in, const int* in_sizes, int n_in,
                              void* d_out, int out_size)
{
    const float* X  = (const float*)d_in[0];
    const float* Wq = (const float*)d_in[1];
    const float* bq = (const float*)d_in[2];
    const float* Wk = (const float*)d_in[3];
    const float* bk = (const float*)d_in[4];
    const float* Wv = (const float*)d_in[5];
    const float* bv = (const float*)d_in[6];
    float* out = (float*)d_out;

    prep_w48<<<48, 256>>>(Wq, Wk, Wv);

    cudaFuncSetAttribute(qkv4, cudaFuncAttributeMaxDynamicSharedMemorySize,
                         QSM4_TOTAL);
    qkv4<<<128, 256, QSM4_TOTAL>>>(X, bq, bk, bv);

    cudaFuncSetAttribute(attn4, cudaFuncAttributeMaxDynamicSharedMemorySize,
                         ASM_TOTAL);
    attn4<<<dim3(32, 4), 256, ASM_TOTAL>>>(out);
}

// round 12
// speedup vs baseline: 1.1740x; 1.1740x over previous
#include <cuda_runtime.h>
#include <cuda_fp16.h>
#include <cstdint>

#define EMBED 2048
#define HD    128
#define NB    4
#define SEQ   2048

// ---------------------------------------------------------------------------
// Scratch globals
// ---------------------------------------------------------------------------
__device__ __align__(16) float g_Wt[3 * HD * EMBED];        // rna-tf32 [w][n][k]
__device__ __align__(16) __half g_qhi[NB * SEQ * HD];       // [b][s][d]
__device__ __align__(16) __half g_qlo[NB * SEQ * HD];
__device__ __align__(16) __half g_k  [NB * SEQ * HD];       // [b][s][d] single fp16
__device__ __align__(16) __half g_vthi[NB * HD * SEQ];      // [b][d][s]
__device__ __align__(16) __half g_vtlo[NB * HD * SEQ];

__device__ __forceinline__ uint32_t pk2h(__half a, __half b) {
    return ((uint32_t)__half_as_ushort(b) << 16) | __half_as_ushort(a);
}
__device__ __forceinline__ uint32_t smem_u32(const void* p) {
    uint32_t a;
    asm("{ .reg .u64 t; cvta.to.shared.u64 t, %1; cvt.u32.u64 %0, t; }"
        : "=r"(a) : "l"(p));
    return a;
}
__device__ __forceinline__ float tf32rna(float x) {
    uint32_t r;
    asm("cvt.rna.tf32.f32 %0, %1;" : "=r"(r) : "f"(x));
    return __uint_as_float(r);
}
// fp16 m16n8k16
__device__ __forceinline__ void mma16816h(float* c, const uint32_t* a,
                                          const uint32_t* b) {
    asm volatile(
        "mma.sync.aligned.m16n8k16.row.col.f32.f16.f16.f32 "
        "{%0,%1,%2,%3}, {%4,%5,%6,%7}, {%8,%9}, {%0,%1,%2,%3};"
        : "+f"(c[0]), "+f"(c[1]), "+f"(c[2]), "+f"(c[3])
        : "r"(a[0]), "r"(a[1]), "r"(a[2]), "r"(a[3]), "r"(b[0]), "r"(b[1]));
}
// tf32 m16n8k8 (fragments via b16 ldmatrix on fp32 data; HW truncates)
__device__ __forceinline__ void mma1688t(float* c, const uint32_t* a,
                                         const uint32_t* b) {
    asm volatile(
        "mma.sync.aligned.m16n8k8.row.col.f32.tf32.tf32.f32 "
        "{%0,%1,%2,%3}, {%4,%5,%6,%7}, {%8,%9}, {%0,%1,%2,%3};"
        : "+f"(c[0]), "+f"(c[1]), "+f"(c[2]), "+f"(c[3])
        : "r"(a[0]), "r"(a[1]), "r"(a[2]), "r"(a[3]), "r"(b[0]), "r"(b[1]));
}
__device__ __forceinline__ void ldsm4(uint32_t* r, uint32_t saddr) {
    asm volatile("ldmatrix.sync.aligned.m8n8.x4.shared.b16 {%0,%1,%2,%3}, [%4];"
                 : "=r"(r[0]), "=r"(r[1]), "=r"(r[2]), "=r"(r[3]) : "r"(saddr));
}
__device__ __forceinline__ void cpa16(uint32_t dst, const void* src) {
    asm volatile("cp.async.cg.shared.global [%0], [%1], 16;"
                 :: "r"(dst), "l"(__cvta_generic_to_global(src)) : "memory");
}
#define CP_COMMIT() asm volatile("cp.async.commit_group;" ::: "memory")
#define CP_WAIT1()  asm volatile("cp.async.wait_group 1;" ::: "memory")

// ---------------------------------------------------------------------------
// prep_w: W fp32 [k][n] -> rna-tf32 fp32 [w][n][k].  grid = 192 (finer tiles).
// ---------------------------------------------------------------------------
__global__ __launch_bounds__(256)
void prep_w(const float* __restrict__ Wq, const float* __restrict__ Wk,
            const float* __restrict__ Wv)
{
    __shared__ float Ws[32][132];
    const int t = threadIdx.x;
    const int w  = blockIdx.x >> 6;
    const int k0 = (blockIdx.x & 63) * 32;
    const float* __restrict__ W = (w == 0) ? Wq : (w == 1 ? Wk : Wv);

    #pragma unroll
    for (int l = 0; l < 16; ++l) {
        int idx = t + l * 256;
        int kk = idx >> 7, n = idx & 127;
        Ws[kk][n] = W[(size_t)(k0 + kk) * HD + n];
    }
    __syncthreads();

    const int n = t >> 1, kh = (t & 1) * 16;
    float* dst = g_Wt + (size_t)w * HD * EMBED + (size_t)n * EMBED + k0 + kh;
    #pragma unroll
    for (int g = 0; g < 4; ++g) {
        float4 v = make_float4(tf32rna(Ws[kh + g * 4 + 0][n]),
                               tf32rna(Ws[kh + g * 4 + 1][n]),
                               tf32rna(Ws[kh + g * 4 + 2][n]),
                               tf32rna(Ws[kh + g * 4 + 3][n]));
        *(float4*)(dst + g * 4) = v;
    }
}

// ---------------------------------------------------------------------------
// qkv3 (R10-passing mainloop): single-term TF32 GEMM, grid (128,3), 3 CTAs/SM.
// A streamed from raw X. Epilogue emits fp16: q hi/lo, k single, vt hi/lo.
// ---------------------------------------------------------------------------
#define KC    32
#define LDW   36
#define LDW16 72
#define A3STG (64 * LDW * 4)
#define B3STG (128 * LDW * 4)
#define O3_A  0
#define O3_B  (2 * A3STG)
#define O3_BIAS (O3_B + 2 * B3STG)
#define QSM3_TOTAL (O3_BIAS + 512)

__global__ __launch_bounds__(256, 3)
void qkv3(const float* __restrict__ X,
          const float* __restrict__ bq, const float* __restrict__ bk,
          const float* __restrict__ bv)
{
    extern __shared__ char smem[];
    const uint32_t sb = smem_u32(smem);
    float* biasS = (float*)(smem + O3_BIAS);

    const int wsel = blockIdx.y;
    const int m0   = blockIdx.x * 64;
    const int t    = threadIdx.x;
    const int wid  = t >> 5, lane = t & 31;
    const int g    = lane >> 2, tig = lane & 3;
    const int wm   = wid >> 2, wn = wid & 3;

    const int aiA = (((lane >> 3) & 1) * 8 + (lane & 7)) * LDW16 + (lane >> 4) * 8;
    const int biB = ((lane >> 4) * 8 + (lane & 7)) * LDW16 + ((lane >> 3) & 1) * 8;

    if (t < 128) {
        const float* bias = (wsel == 0) ? bq : (wsel == 1 ? bk : bv);
        biasS[t] = bias[t];
    }

    const float* Wt = g_Wt + (size_t)wsel * HD * EMBED;
    const int ar = t >> 2, ac = t & 3;
    const int br = t >> 1, bh = t & 1;

    float c[2][4][4];
    #pragma unroll
    for (int i = 0; i < 2; ++i)
        #pragma unroll
        for (int j = 0; j < 4; ++j)
            #pragma unroll
            for (int q = 0; q < 4; ++q) c[i][j][q] = 0.f;

    #pragma unroll
    for (int pi = 0; pi < 2; ++pi) {
        const int kb = pi * KC;
        {
            const float* src = X + (size_t)(m0 + ar) * EMBED + kb + ac * 8;
            const uint32_t dst = sb + O3_A + pi * A3STG + ar * (LDW * 4) + ac * 32;
            cpa16(dst, src);
            cpa16(dst + 16, src + 4);
        }
        {
            const float* src = Wt + (size_t)br * EMBED + kb + bh * 16;
            const uint32_t dst = sb + O3_B + pi * B3STG + br * (LDW * 4) + bh * 64;
            #pragma unroll
            for (int j = 0; j < 4; ++j) cpa16(dst + j * 16, src + j * 4);
        }
        CP_COMMIT();
    }

    for (int kt = 0; kt < EMBED / KC; ++kt) {
        const int st = kt & 1;
        const uint32_t sA = sb + O3_A + st * A3STG;
        const uint32_t sB = sb + O3_B + st * B3STG;

        CP_WAIT1();
        __syncthreads();

        #pragma unroll
        for (int ks = 0; ks < 4; ++ks) {
            const int ko = ks * 16;
            uint32_t a[2][4], bb[2][4];
            #pragma unroll
            for (int mi = 0; mi < 2; ++mi)
                ldsm4(a[mi], sA + 2 * ((wm * 32 + mi * 16) * LDW16 + ko + aiA));
            #pragma unroll
            for (int h = 0; h < 2; ++h)
                ldsm4(bb[h], sB + 2 * ((wn * 32 + h * 16) * LDW16 + ko + biB));
            #pragma unroll
            for (int mi = 0; mi < 2; ++mi)
                #pragma unroll
                for (int nt = 0; nt < 4; ++nt)
                    mma1688t(c[mi][nt], a[mi], &bb[nt >> 1][(nt & 1) * 2]);
        }
        __syncthreads();

        if (kt + 2 < EMBED / KC) {
            const int kb = (kt + 2) * KC;
            {
                const float* src = X + (size_t)(m0 + ar) * EMBED + kb + ac * 8;
                const uint32_t dst = sb + O3_A + st * A3STG + ar * (LDW * 4) + ac * 32;
                cpa16(dst, src);
                cpa16(dst + 16, src + 4);
            }
            {
                const float* src = Wt + (size_t)br * EMBED + kb + bh * 16;
                const uint32_t dst = sb + O3_B + st * B3STG + br * (LDW * 4) + bh * 64;
                #pragma unroll
                for (int j = 0; j < 4; ++j) cpa16(dst + j * 16, src + j * 4);
            }
        }
        CP_COMMIT();
    }

    // ---- epilogue: frags (+bias) -> Ct -> fp16 gmem
    __syncthreads();
    float (*Ct)[132] = (float (*)[132])smem;
    #pragma unroll
    for (int mi = 0; mi < 2; ++mi) {
        const int r = wm * 32 + mi * 16 + g;
        #pragma unroll
        for (int nt = 0; nt < 4; ++nt) {
            const int n = wn * 32 + nt * 8 + tig * 2;
            Ct[r][n]         = c[mi][nt][0] + biasS[n];
            Ct[r][n + 1]     = c[mi][nt][1] + biasS[n + 1];
            Ct[r + 8][n]     = c[mi][nt][2] + biasS[n];
            Ct[r + 8][n + 1] = c[mi][nt][3] + biasS[n + 1];
        }
    }
    __syncthreads();

    const int batch = m0 >> 11, s0 = m0 & 2047;
    if (wsel == 0) {
        // q: hi/lo fp16 [b][s][d]
        const int r = t >> 2, dq = (t & 3) * 32;
        __half* dhi = g_qhi + ((size_t)batch * SEQ + s0 + r) * HD + dq;
        __half* dlo = g_qlo + ((size_t)batch * SEQ + s0 + r) * HD + dq;
        #pragma unroll
        for (int qq = 0; qq < 4; ++qq) {
            uint32_t hp[4], lp[4];
            #pragma unroll
            for (int e = 0; e < 4; ++e) {
                float x0 = Ct[r][dq + qq * 8 + e * 2];
                float x1 = Ct[r][dq + qq * 8 + e * 2 + 1];
                __half h0 = __float2half(x0);
                __half h1 = __float2half(x1);
                hp[e] = pk2h(h0, h1);
                lp[e] = pk2h(__float2half(x0 - __half2float(h0)),
                             __float2half(x1 - __half2float(h1)));
            }
            *(uint4*)(dhi + qq * 8) = make_uint4(hp[0], hp[1], hp[2], hp[3]);
            *(uint4*)(dlo + qq * 8) = make_uint4(lp[0], lp[1], lp[2], lp[3]);
        }
    } else if (wsel == 1) {
        // k: single fp16 [b][s][d]
        const int r = t >> 2, dq = (t & 3) * 32;
        __half* dst = g_k + ((size_t)batch * SEQ + s0 + r) * HD + dq;
        #pragma unroll
        for (int qq = 0; qq < 4; ++qq) {
            uint32_t hp[4];
            #pragma unroll
            for (int e = 0; e < 4; ++e)
                hp[e] = pk2h(__float2half(Ct[r][dq + qq * 8 + e * 2]),
                             __float2half(Ct[r][dq + qq * 8 + e * 2 + 1]));
            *(uint4*)(dst + qq * 8) = make_uint4(hp[0], hp[1], hp[2], hp[3]);
        }
    } else {
        // v: transposed hi/lo fp16 [b][d][s]
        const int d = t >> 1, sch = (t & 1) * 32;
        size_t base = ((size_t)batch * HD + d) * SEQ + s0 + sch;
        #pragma unroll
        for (int qq = 0; qq < 4; ++qq) {
            uint32_t hp[4], lp[4];
            #pragma unroll
            for (int e = 0; e < 4; ++e) {
                float x0 = Ct[sch + qq * 8 + e * 2][d];
                float x1 = Ct[sch + qq * 8 + e * 2 + 1][d];
                __half h0 = __float2half(x0);
                __half h1 = __float2half(x1);
                hp[e] = pk2h(h0, h1);
                lp[e] = pk2h(__float2half(x0 - __half2float(h0)),
                             __float2half(x1 - __half2float(h1)));
            }
            *(uint4*)(g_vthi + base + qq * 8) = make_uint4(hp[0], hp[1], hp[2], hp[3]);
            *(uint4*)(g_vtlo + base + qq * 8) = make_uint4(lp[0], lp[1], lp[2], lp[3]);
        }
    }
}

// ---------------------------------------------------------------------------
// attn6: fp16 flash attention. Q hi/lo + K single (QK: 2 MMA/group);
// P single + V hi/lo (PV: 2 MMA/group). Same loop structure as attn4.
// cp.async 2-stage pipeline, 64-wide k-subtiles, balanced causal pairing.
// ---------------------------------------------------------------------------
#define KT   64
#define LDK  136
#define LDV  72
#define LDP  72
#define SPS  68
#define KSTG (KT * LDK * 2)      // 17408
#define VSTG (HD * LDV * 2)      // 18432

#define AO_QHI  0
#define AO_QLO  (AO_QHI + 32 * LDK * 2)          // 8704
#define AO_K    (AO_QLO + 32 * LDK * 2)          // 17408
#define AO_VHI  (AO_K   + 2 * KSTG)              // 52224
#define AO_VLO  (AO_VHI + 2 * VSTG)              // 89088
#define AO_PS   (AO_VLO + 2 * VSTG)              // 125952
#define AO_PB   (AO_PS  + 32 * SPS * 4)          // 134656
#define AO_MLA  (AO_PB  + 32 * LDP * 2)          // 139264
#define ASM_TOTAL (AO_MLA + 3 * 32 * 4)          // 139648

__global__ __launch_bounds__(256)
void attn6(float* __restrict__ out)
{
    extern __shared__ char smem[];
    const uint32_t sb = smem_u32(smem);
    float* Ps   = (float*)(smem + AO_PS);
    float* m_s  = (float*)(smem + AO_MLA);
    float* l_s  = m_s + 32;
    float* al_s = l_s + 32;

    const int b = blockIdx.y, t = threadIdx.x;
    const int wid = t >> 5, lane = t & 31;
    const int g = lane >> 2, tig = lane & 3;
    const int wm = wid & 1, wn = wid >> 1;

    const int aiQ = (((lane >> 3) & 1) * 8 + (lane & 7)) * LDK + (lane >> 4) * 8;
    const int biK = ((lane >> 4) * 8 + (lane & 7)) * LDK + ((lane >> 3) & 1) * 8;
    const int aiP = (((lane >> 3) & 1) * 8 + (lane & 7)) * LDP + (lane >> 4) * 8;
    const int biV = ((lane >> 4) * 8 + (lane & 7)) * LDV + ((lane >> 3) & 1) * 8;

    const __half* gQh = g_qhi + (size_t)b * SEQ * HD;
    const __half* gQl = g_qlo + (size_t)b * SEQ * HD;
    const __half* gK  = g_k   + (size_t)b * SEQ * HD;
    const __half* gVh = g_vthi + (size_t)b * HD * SEQ;
    const __half* gVl = g_vtlo + (size_t)b * HD * SEQ;

    const float RSC = 0.08838834764831845f;
    const int sr = t >> 3, sc0 = (t & 7) * 8;
    const int kr = t >> 2, kq = t & 3;
    const int vr = t >> 1, vhh = t & 1;

    for (int subt = 0; subt < 2; ++subt) {
        const int jt = subt ? (63 - blockIdx.x) : blockIdx.x;
        const int q0 = jt * 32;
        const int iters = (jt >> 1) + 1;

        {
            const int r = t >> 3, dq = (t & 7) * 16;
            const __half* sh = gQh + (size_t)(q0 + r) * HD + dq;
            const __half* sl = gQl + (size_t)(q0 + r) * HD + dq;
            *(uint4*)(smem + AO_QHI + (r * LDK + dq) * 2)      = *(const uint4*)sh;
            *(uint4*)(smem + AO_QHI + (r * LDK + dq + 8) * 2)  = *(const uint4*)(sh + 8);
            *(uint4*)(smem + AO_QLO + (r * LDK + dq) * 2)      = *(const uint4*)sl;
            *(uint4*)(smem + AO_QLO + (r * LDK + dq + 8) * 2)  = *(const uint4*)(sl + 8);
        }
        if (t < 32) { m_s[t] = -1e30f; l_s[t] = 0.f; }

        float o[4][4];
        #pragma unroll
        for (int nt = 0; nt < 4; ++nt)
            #pragma unroll
            for (int q = 0; q < 4; ++q) o[nt][q] = 0.f;

        #pragma unroll
        for (int pi = 0; pi < 2; ++pi) {
            if (pi < iters) {
                const int k0 = pi * KT;
                const uint32_t k_d  = sb + AO_K   + pi * KSTG + kr * (LDK * 2) + kq * 64;
                const uint32_t vh_d = sb + AO_VHI + pi * VSTG + vr * (LDV * 2) + vhh * 64;
                const uint32_t vl_d = sb + AO_VLO + pi * VSTG + vr * (LDV * 2) + vhh * 64;
                const __half* ks  = gK  + (size_t)(k0 + kr) * HD + kq * 32;
                const __half* vsh = gVh + (size_t)vr * SEQ + k0 + vhh * 32;
                const __half* vsl = gVl + (size_t)vr * SEQ + k0 + vhh * 32;
                #pragma unroll
                for (int j = 0; j < 4; ++j) {
                    cpa16(k_d  + j * 16, ks  + j * 8);
                    cpa16(vh_d + j * 16, vsh + j * 8);
                    cpa16(vl_d + j * 16, vsl + j * 8);
                }
            }
            CP_COMMIT();
        }

        for (int it = 0; it < iters; ++it) {
            const int k0 = it * KT;
            const int st = it & 1;
            const uint32_t sK   = sb + AO_K   + st * KSTG;
            const uint32_t sVhi = sb + AO_VHI + st * VSTG;
            const uint32_t sVlo = sb + AO_VLO + st * VSTG;

            CP_WAIT1();
            __syncthreads();

            // ---- QK^T: S = Qhi*K + Qlo*K
            float s4[2][4];
            #pragma unroll
            for (int nt = 0; nt < 2; ++nt)
                #pragma unroll
                for (int q = 0; q < 4; ++q) s4[nt][q] = 0.f;
            #pragma unroll
            for (int ks = 0; ks < 8; ++ks) {
                const int k0s = ks * 16;
                uint32_t qh[4], ql[4], kk[4];
                const uint32_t ao = 2 * (wm * 16 * LDK + k0s + aiQ);
                ldsm4(qh, sb + AO_QHI + ao);
                ldsm4(ql, sb + AO_QLO + ao);
                ldsm4(kk, sK + 2 * (wn * 16 * LDK + k0s + biK));
                #pragma unroll
                for (int nt = 0; nt < 2; ++nt) {
                    mma16816h(s4[nt], qh, &kk[nt * 2]);
                    mma16816h(s4[nt], ql, &kk[nt * 2]);
                }
            }
            {
                const int row0 = wm * 16 + g;
                #pragma unroll
                for (int nt = 0; nt < 2; ++nt) {
                    const int col = wn * 16 + nt * 8 + tig * 2;
                    *(float2*)&Ps[row0 * SPS + col] = make_float2(s4[nt][0], s4[nt][1]);
                    *(float2*)&Ps[(row0 + 8) * SPS + col] = make_float2(s4[nt][2], s4[nt][3]);
                }
            }
            __syncthreads();

            // ---- softmax; pack P single fp16
            {
                const int gq = q0 + sr;
                float sv[8];
                float rm = -1e30f;
                #pragma unroll
                for (int j = 0; j < 8; ++j) {
                    float v = Ps[sr * SPS + sc0 + j] * RSC;
                    if (k0 + sc0 + j > gq) v = -1e10f;
                    sv[j] = v;
                    rm = fmaxf(rm, v);
                }
                #pragma unroll
                for (int off = 4; off >= 1; off >>= 1)
                    rm = fmaxf(rm, __shfl_xor_sync(0xffffffffu, rm, off));
                const float mo = m_s[sr];
                const float mn = fmaxf(mo, rm);
                float rs = 0.f;
                uint32_t pph[4];
                #pragma unroll
                for (int j = 0; j < 4; ++j) {
                    float p0 = __expf(sv[2 * j] - mn);
                    float p1 = __expf(sv[2 * j + 1] - mn);
                    rs += p0 + p1;
                    pph[j] = pk2h(__float2half(p0), __float2half(p1));
                }
                #pragma unroll
                for (int off = 4; off >= 1; off >>= 1)
                    rs += __shfl_xor_sync(0xffffffffu, rs, off);
                *(uint4*)(smem + AO_PB + (sr * LDP + sc0) * 2) =
                    make_uint4(pph[0], pph[1], pph[2], pph[3]);
                if ((t & 7) == 0) {
                    const float al = __expf(mo - mn);
                    m_s[sr]  = mn;
                    al_s[sr] = al;
                    l_s[sr]  = l_s[sr] * al + rs;
                }
            }
            __syncthreads();

            // ---- PV: O = alpha*O + P*Vhi + P*Vlo
            {
                const float a0 = al_s[wm * 16 + g];
                const float a1 = al_s[wm * 16 + g + 8];
                #pragma unroll
                for (int nt = 0; nt < 4; ++nt) {
                    o[nt][0] *= a0; o[nt][1] *= a0;
                    o[nt][2] *= a1; o[nt][3] *= a1;
                }
                #pragma unroll
                for (int ks = 0; ks < 4; ++ks) {
                    const int k0s = ks * 16;
                    uint32_t pa[4], vh[2][4], vl[2][4];
                    ldsm4(pa, sb + AO_PB + 2 * (wm * 16 * LDP + k0s + aiP));
                    #pragma unroll
                    for (int h = 0; h < 2; ++h) {
                        const uint32_t bo = 2 * ((wn * 32 + h * 16) * LDV + k0s + biV);
                        ldsm4(vh[h], sVhi + bo);
                        ldsm4(vl[h], sVlo + bo);
                    }
                    #pragma unroll
                    for (int nt = 0; nt < 4; ++nt) {
                        mma16816h(o[nt], pa, &vh[nt >> 1][(nt & 1) * 2]);
                        mma16816h(o[nt], pa, &vl[nt >> 1][(nt & 1) * 2]);
                    }
                }
            }
            __syncthreads();

            if (it + 2 < iters) {
                const int kn = (it + 2) * KT;
                const uint32_t k_d  = sb + AO_K   + st * KSTG + kr * (LDK * 2) + kq * 64;
                const uint32_t vh_d = sb + AO_VHI + st * VSTG + vr * (LDV * 2) + vhh * 64;
                const uint32_t vl_d = sb + AO_VLO + st * VSTG + vr * (LDV * 2) + vhh * 64;
                const __half* ks  = gK  + (size_t)(kn + kr) * HD + kq * 32;
                const __half* vsh = gVh + (size_t)vr * SEQ + kn + vhh * 32;
                const __half* vsl = gVl + (size_t)vr * SEQ + kn + vhh * 32;
                #pragma unroll
                for (int j = 0; j < 4; ++j) {
                    cpa16(k_d  + j * 16, ks  + j * 8);
                    cpa16(vh_d + j * 16, vsh + j * 8);
                    cpa16(vl_d + j * 16, vsl + j * 8);
                }
            }
            CP_COMMIT();
        }

        {
            const float li0 = 1.f / l_s[wm * 16 + g];
            const float li1 = 1.f / l_s[wm * 16 + g + 8];
            float* op0 = out + ((size_t)b * SEQ + q0 + wm * 16 + g) * HD;
            float* op1 = op0 + 8 * HD;
            #pragma unroll
            for (int nt = 0; nt < 4; ++nt) {
                const int d = wn * 32 + nt * 8 + tig * 2;
                *(float2*)(op0 + d) = make_float2(o[nt][0] * li0, o[nt][1] * li0);
                *(float2*)(op1 + d) = make_float2(o[nt][2] * li1, o[nt][3] * li1);
            }
        }
        __syncthreads();
    }
}

// ---------------------------------------------------------------------------
extern "C" void kernel_launch(void* const* d_in, const int* in_sizes, int n_in,
                              void* d_out, int out_size)
{
    const float* X  = (const float*)d_in[0];
    const float* Wq = (const float*)d_in[1];
    const float* bq = (const float*)d_in[2];
    const float* Wk = (const float*)d_in[3];
    const float* bk = (const float*)d_in[4];
    const float* Wv = (const float*)d_in[5];
    const float* bv = (const float*)d_in[6];
    float* out = (float*)d_out;

    prep_w<<<192, 256>>>(Wq, Wk, Wv);

    cudaFuncSetAttribute(qkv3, cudaFuncAttributeMaxDynamicSharedMemorySize,
                         QSM3_TOTAL);
    qkv3<<<dim3(128, 3), 256, QSM3_TOTAL>>>(X, bq, bk, bv);

    cudaFuncSetAttribute(attn6, cudaFuncAttributeMaxDynamicSharedMemorySize,
                         ASM_TOTAL);
    attn6<<<dim3(32, 4), 256, ASM_TOTAL>>>(out);
}

// round 13
// speedup vs baseline: 1.3226x; 1.1266x over previous
#include <cuda_runtime.h>
#include <cuda_fp16.h>
#include <cstdint>

#define EMBED 2048
#define HD    128
#define NB    4
#define SEQ   2048

// ---------------------------------------------------------------------------
// Scratch globals
// ---------------------------------------------------------------------------
__device__ __align__(16) float g_Wt[3 * HD * EMBED];        // rna-tf32 [w][n][k]
__device__ __align__(16) __half g_q [NB * SEQ * HD];        // [b][s][d] fp16
__device__ __align__(16) __half g_k [NB * SEQ * HD];        // [b][s][d] fp16
__device__ __align__(16) __half g_vt[NB * HD * SEQ];        // [b][d][s] fp16

__device__ __forceinline__ uint32_t pk2h(__half a, __half b) {
    return ((uint32_t)__half_as_ushort(b) << 16) | __half_as_ushort(a);
}
__device__ __forceinline__ uint32_t smem_u32(const void* p) {
    uint32_t a;
    asm("{ .reg .u64 t; cvta.to.shared.u64 t, %1; cvt.u32.u64 %0, t; }"
        : "=r"(a) : "l"(p));
    return a;
}
__device__ __forceinline__ float tf32rna(float x) {
    uint32_t r;
    asm("cvt.rna.tf32.f32 %0, %1;" : "=r"(r) : "f"(x));
    return __uint_as_float(r);
}
// fp16 m16n8k16
__device__ __forceinline__ void mma16816h(float* c, const uint32_t* a,
                                          const uint32_t* b) {
    asm volatile(
        "mma.sync.aligned.m16n8k16.row.col.f32.f16.f16.f32 "
        "{%0,%1,%2,%3}, {%4,%5,%6,%7}, {%8,%9}, {%0,%1,%2,%3};"
        : "+f"(c[0]), "+f"(c[1]), "+f"(c[2]), "+f"(c[3])
        : "r"(a[0]), "r"(a[1]), "r"(a[2]), "r"(a[3]), "r"(b[0]), "r"(b[1]));
}
// tf32 m16n8k8 (fragments via b16 ldmatrix on fp32 data; HW truncates)
__device__ __forceinline__ void mma1688t(float* c, const uint32_t* a,
                                         const uint32_t* b) {
    asm volatile(
        "mma.sync.aligned.m16n8k8.row.col.f32.tf32.tf32.f32 "
        "{%0,%1,%2,%3}, {%4,%5,%6,%7}, {%8,%9}, {%0,%1,%2,%3};"
        : "+f"(c[0]), "+f"(c[1]), "+f"(c[2]), "+f"(c[3])
        : "r"(a[0]), "r"(a[1]), "r"(a[2]), "r"(a[3]), "r"(b[0]), "r"(b[1]));
}
__device__ __forceinline__ void ldsm4(uint32_t* r, uint32_t saddr) {
    asm volatile("ldmatrix.sync.aligned.m8n8.x4.shared.b16 {%0,%1,%2,%3}, [%4];"
                 : "=r"(r[0]), "=r"(r[1]), "=r"(r[2]), "=r"(r[3]) : "r"(saddr));
}
__device__ __forceinline__ void cpa16(uint32_t dst, const void* src) {
    asm volatile("cp.async.cg.shared.global [%0], [%1], 16;"
                 :: "r"(dst), "l"(__cvta_generic_to_global(src)) : "memory");
}
#define CP_COMMIT() asm volatile("cp.async.commit_group;" ::: "memory")
#define CP_WAIT1()  asm volatile("cp.async.wait_group 1;" ::: "memory")

// ---------------------------------------------------------------------------
// prep_w (unchanged, passing): W fp32 [k][n] -> rna-tf32 fp32 [w][n][k]
// ---------------------------------------------------------------------------
__global__ __launch_bounds__(256)
void prep_w(const float* __restrict__ Wq, const float* __restrict__ Wk,
            const float* __restrict__ Wv)
{
    __shared__ float Ws[32][132];
    const int t = threadIdx.x;
    const int w  = blockIdx.x >> 6;
    const int k0 = (blockIdx.x & 63) * 32;
    const float* __restrict__ W = (w == 0) ? Wq : (w == 1 ? Wk : Wv);

    #pragma unroll
    for (int l = 0; l < 16; ++l) {
        int idx = t + l * 256;
        int kk = idx >> 7, n = idx & 127;
        Ws[kk][n] = W[(size_t)(k0 + kk) * HD + n];
    }
    __syncthreads();

    const int n = t >> 1, kh = (t & 1) * 16;
    float* dst = g_Wt + (size_t)w * HD * EMBED + (size_t)n * EMBED + k0 + kh;
    #pragma unroll
    for (int g = 0; g < 4; ++g) {
        float4 v = make_float4(tf32rna(Ws[kh + g * 4 + 0][n]),
                               tf32rna(Ws[kh + g * 4 + 1][n]),
                               tf32rna(Ws[kh + g * 4 + 2][n]),
                               tf32rna(Ws[kh + g * 4 + 3][n]));
        *(float4*)(dst + g * 4) = v;
    }
}

// ---------------------------------------------------------------------------
// qkv3 (R10/R12-passing mainloop): single-term TF32 GEMM, grid (128,3),
// 3 CTAs/SM. Epilogue: q,k single fp16 [b][s][d]; v single fp16 [b][d][s].
// ---------------------------------------------------------------------------
#define KC    32
#define LDW   36
#define LDW16 72
#define A3STG (64 * LDW * 4)
#define B3STG (128 * LDW * 4)
#define O3_A  0
#define O3_B  (2 * A3STG)
#define O3_BIAS (O3_B + 2 * B3STG)
#define QSM3_TOTAL (O3_BIAS + 512)

__global__ __launch_bounds__(256, 3)
void qkv3(const float* __restrict__ X,
          const float* __restrict__ bq, const float* __restrict__ bk,
          const float* __restrict__ bv)
{
    extern __shared__ char smem[];
    const uint32_t sb = smem_u32(smem);
    float* biasS = (float*)(smem + O3_BIAS);

    const int wsel = blockIdx.y;
    const int m0   = blockIdx.x * 64;
    const int t    = threadIdx.x;
    const int wid  = t >> 5, lane = t & 31;
    const int g    = lane >> 2, tig = lane & 3;
    const int wm   = wid >> 2, wn = wid & 3;

    const int aiA = (((lane >> 3) & 1) * 8 + (lane & 7)) * LDW16 + (lane >> 4) * 8;
    const int biB = ((lane >> 4) * 8 + (lane & 7)) * LDW16 + ((lane >> 3) & 1) * 8;

    if (t < 128) {
        const float* bias = (wsel == 0) ? bq : (wsel == 1 ? bk : bv);
        biasS[t] = bias[t];
    }

    const float* Wt = g_Wt + (size_t)wsel * HD * EMBED;
    const int ar = t >> 2, ac = t & 3;
    const int br = t >> 1, bh = t & 1;

    float c[2][4][4];
    #pragma unroll
    for (int i = 0; i < 2; ++i)
        #pragma unroll
        for (int j = 0; j < 4; ++j)
            #pragma unroll
            for (int q = 0; q < 4; ++q) c[i][j][q] = 0.f;

    #pragma unroll
    for (int pi = 0; pi < 2; ++pi) {
        const int kb = pi * KC;
        {
            const float* src = X + (size_t)(m0 + ar) * EMBED + kb + ac * 8;
            const uint32_t dst = sb + O3_A + pi * A3STG + ar * (LDW * 4) + ac * 32;
            cpa16(dst, src);
            cpa16(dst + 16, src + 4);
        }
        {
            const float* src = Wt + (size_t)br * EMBED + kb + bh * 16;
            const uint32_t dst = sb + O3_B + pi * B3STG + br * (LDW * 4) + bh * 64;
            #pragma unroll
            for (int j = 0; j < 4; ++j) cpa16(dst + j * 16, src + j * 4);
        }
        CP_COMMIT();
    }

    for (int kt = 0; kt < EMBED / KC; ++kt) {
        const int st = kt & 1;
        const uint32_t sA = sb + O3_A + st * A3STG;
        const uint32_t sB = sb + O3_B + st * B3STG;

        CP_WAIT1();
        __syncthreads();

        #pragma unroll
        for (int ks = 0; ks < 4; ++ks) {
            const int ko = ks * 16;
            uint32_t a[2][4], bb[2][4];
            #pragma unroll
            for (int mi = 0; mi < 2; ++mi)
                ldsm4(a[mi], sA + 2 * ((wm * 32 + mi * 16) * LDW16 + ko + aiA));
            #pragma unroll
            for (int h = 0; h < 2; ++h)
                ldsm4(bb[h], sB + 2 * ((wn * 32 + h * 16) * LDW16 + ko + biB));
            #pragma unroll
            for (int mi = 0; mi < 2; ++mi)
                #pragma unroll
                for (int nt = 0; nt < 4; ++nt)
                    mma1688t(c[mi][nt], a[mi], &bb[nt >> 1][(nt & 1) * 2]);
        }
        __syncthreads();

        if (kt + 2 < EMBED / KC) {
            const int kb = (kt + 2) * KC;
            {
                const float* src = X + (size_t)(m0 + ar) * EMBED + kb + ac * 8;
                const uint32_t dst = sb + O3_A + st * A3STG + ar * (LDW * 4) + ac * 32;
                cpa16(dst, src);
                cpa16(dst + 16, src + 4);
            }
            {
                const float* src = Wt + (size_t)br * EMBED + kb + bh * 16;
                const uint32_t dst = sb + O3_B + st * B3STG + br * (LDW * 4) + bh * 64;
                #pragma unroll
                for (int j = 0; j < 4; ++j) cpa16(dst + j * 16, src + j * 4);
            }
        }
        CP_COMMIT();
    }

    // ---- epilogue: frags (+bias) -> Ct -> single fp16 gmem
    __syncthreads();
    float (*Ct)[132] = (float (*)[132])smem;
    #pragma unroll
    for (int mi = 0; mi < 2; ++mi) {
        const int r = wm * 32 + mi * 16 + g;
        #pragma unroll
        for (int nt = 0; nt < 4; ++nt) {
            const int n = wn * 32 + nt * 8 + tig * 2;
            Ct[r][n]         = c[mi][nt][0] + biasS[n];
            Ct[r][n + 1]     = c[mi][nt][1] + biasS[n + 1];
            Ct[r + 8][n]     = c[mi][nt][2] + biasS[n];
            Ct[r + 8][n + 1] = c[mi][nt][3] + biasS[n + 1];
        }
    }
    __syncthreads();

    const int batch = m0 >> 11, s0 = m0 & 2047;
    if (wsel < 2) {
        // q / k: single fp16 [b][s][d]
        const int r = t >> 2, dq = (t & 3) * 32;
        __half* dst = (wsel == 0 ? g_q : g_k)
            + ((size_t)batch * SEQ + s0 + r) * HD + dq;
        #pragma unroll
        for (int qq = 0; qq < 4; ++qq) {
            uint32_t hp[4];
            #pragma unroll
            for (int e = 0; e < 4; ++e)
                hp[e] = pk2h(__float2half(Ct[r][dq + qq * 8 + e * 2]),
                             __float2half(Ct[r][dq + qq * 8 + e * 2 + 1]));
            *(uint4*)(dst + qq * 8) = make_uint4(hp[0], hp[1], hp[2], hp[3]);
        }
    } else {
        // v: single fp16 transposed [b][d][s]
        const int d = t >> 1, sch = (t & 1) * 32;
        __half* dst = g_vt + ((size_t)batch * HD + d) * SEQ + s0 + sch;
        #pragma unroll
        for (int qq = 0; qq < 4; ++qq) {
            uint32_t hp[4];
            #pragma unroll
            for (int e = 0; e < 4; ++e)
                hp[e] = pk2h(__float2half(Ct[sch + qq * 8 + e * 2][d]),
                             __float2half(Ct[sch + qq * 8 + e * 2 + 1][d]));
            *(uint4*)(dst + qq * 8) = make_uint4(hp[0], hp[1], hp[2], hp[3]);
        }
    }
}

// ---------------------------------------------------------------------------
// attn7: all-single-fp16 flash attention. QK: 1 MMA/group; PV: 1 MMA/group.
// Same loop structure as attn6 (KT=64, cp.async 2-stage, balanced pairing).
// grid (32, 4).
// ---------------------------------------------------------------------------
#define KT   64
#define LDK  136
#define LDV  72
#define LDP  72
#define SPS  68
#define KSTG (KT * LDK * 2)      // 17408
#define VSTG (HD * LDV * 2)      // 18432

#define AO_Q    0                                // 32*136*2 = 8704
#define AO_K    (AO_Q + 32 * LDK * 2)            // 8704;  2*17408
#define AO_V    (AO_K + 2 * KSTG)                // 43520; 2*18432
#define AO_PS   (AO_V + 2 * VSTG)                // 80384; 8704
#define AO_PB   (AO_PS + 32 * SPS * 4)           // 89088; 4608
#define AO_MLA  (AO_PB + 32 * LDP * 2)           // 93696
#define ASM_TOTAL (AO_MLA + 3 * 32 * 4)          // 94080

__global__ __launch_bounds__(256)
void attn7(float* __restrict__ out)
{
    extern __shared__ char smem[];
    const uint32_t sb = smem_u32(smem);
    float* Ps   = (float*)(smem + AO_PS);
    float* m_s  = (float*)(smem + AO_MLA);
    float* l_s  = m_s + 32;
    float* al_s = l_s + 32;

    const int b = blockIdx.y, t = threadIdx.x;
    const int wid = t >> 5, lane = t & 31;
    const int g = lane >> 2, tig = lane & 3;
    const int wm = wid & 1, wn = wid >> 1;

    const int aiQ = (((lane >> 3) & 1) * 8 + (lane & 7)) * LDK + (lane >> 4) * 8;
    const int biK = ((lane >> 4) * 8 + (lane & 7)) * LDK + ((lane >> 3) & 1) * 8;
    const int aiP = (((lane >> 3) & 1) * 8 + (lane & 7)) * LDP + (lane >> 4) * 8;
    const int biV = ((lane >> 4) * 8 + (lane & 7)) * LDV + ((lane >> 3) & 1) * 8;

    const __half* gQ  = g_q  + (size_t)b * SEQ * HD;
    const __half* gK  = g_k  + (size_t)b * SEQ * HD;
    const __half* gVt = g_vt + (size_t)b * HD * SEQ;

    const float RSC = 0.08838834764831845f;
    const int sr = t >> 3, sc0 = (t & 7) * 8;
    const int kr = t >> 2, kq = t & 3;
    const int vr = t >> 1, vhh = t & 1;

    for (int subt = 0; subt < 2; ++subt) {
        const int jt = subt ? (63 - blockIdx.x) : blockIdx.x;
        const int q0 = jt * 32;
        const int iters = (jt >> 1) + 1;

        {
            const int r = t >> 3, dq = (t & 7) * 16;
            const __half* sh = gQ + (size_t)(q0 + r) * HD + dq;
            *(uint4*)(smem + AO_Q + (r * LDK + dq) * 2)     = *(const uint4*)sh;
            *(uint4*)(smem + AO_Q + (r * LDK + dq + 8) * 2) = *(const uint4*)(sh + 8);
        }
        if (t < 32) { m_s[t] = -1e30f; l_s[t] = 0.f; }

        float o[4][4];
        #pragma unroll
        for (int nt = 0; nt < 4; ++nt)
            #pragma unroll
            for (int q = 0; q < 4; ++q) o[nt][q] = 0.f;

        #pragma unroll
        for (int pi = 0; pi < 2; ++pi) {
            if (pi < iters) {
                const int k0 = pi * KT;
                const uint32_t k_d = sb + AO_K + pi * KSTG + kr * (LDK * 2) + kq * 64;
                const uint32_t v_d = sb + AO_V + pi * VSTG + vr * (LDV * 2) + vhh * 64;
                const __half* ks = gK  + (size_t)(k0 + kr) * HD + kq * 32;
                const __half* vs = gVt + (size_t)vr * SEQ + k0 + vhh * 32;
                #pragma unroll
                for (int j = 0; j < 4; ++j) {
                    cpa16(k_d + j * 16, ks + j * 8);
                    cpa16(v_d + j * 16, vs + j * 8);
                }
            }
            CP_COMMIT();
        }

        for (int it = 0; it < iters; ++it) {
            const int k0 = it * KT;
            const int st = it & 1;
            const uint32_t sK = sb + AO_K + st * KSTG;
            const uint32_t sV = sb + AO_V + st * VSTG;

            CP_WAIT1();
            __syncthreads();

            // ---- QK^T: S = Q*K (single fp16)
            float s4[2][4];
            #pragma unroll
            for (int nt = 0; nt < 2; ++nt)
                #pragma unroll
                for (int q = 0; q < 4; ++q) s4[nt][q] = 0.f;
            #pragma unroll
            for (int ks = 0; ks < 8; ++ks) {
                const int k0s = ks * 16;
                uint32_t qa[4], kk[4];
                ldsm4(qa, sb + AO_Q + 2 * (wm * 16 * LDK + k0s + aiQ));
                ldsm4(kk, sK + 2 * (wn * 16 * LDK + k0s + biK));
                #pragma unroll
                for (int nt = 0; nt < 2; ++nt)
                    mma16816h(s4[nt], qa, &kk[nt * 2]);
            }
            {
                const int row0 = wm * 16 + g;
                #pragma unroll
                for (int nt = 0; nt < 2; ++nt) {
                    const int col = wn * 16 + nt * 8 + tig * 2;
                    *(float2*)&Ps[row0 * SPS + col] = make_float2(s4[nt][0], s4[nt][1]);
                    *(float2*)&Ps[(row0 + 8) * SPS + col] = make_float2(s4[nt][2], s4[nt][3]);
                }
            }
            __syncthreads();

            // ---- softmax; pack P single fp16
            {
                const int gq = q0 + sr;
                float sv[8];
                float rm = -1e30f;
                #pragma unroll
                for (int j = 0; j < 8; ++j) {
                    float v = Ps[sr * SPS + sc0 + j] * RSC;
                    if (k0 + sc0 + j > gq) v = -1e10f;
                    sv[j] = v;
                    rm = fmaxf(rm, v);
                }
                #pragma unroll
                for (int off = 4; off >= 1; off >>= 1)
                    rm = fmaxf(rm, __shfl_xor_sync(0xffffffffu, rm, off));
                const float mo = m_s[sr];
                const float mn = fmaxf(mo, rm);
                float rs = 0.f;
                uint32_t pph[4];
                #pragma unroll
                for (int j = 0; j < 4; ++j) {
                    float p0 = __expf(sv[2 * j] - mn);
                    float p1 = __expf(sv[2 * j + 1] - mn);
                    rs += p0 + p1;
                    pph[j] = pk2h(__float2half(p0), __float2half(p1));
                }
                #pragma unroll
                for (int off = 4; off >= 1; off >>= 1)
                    rs += __shfl_xor_sync(0xffffffffu, rs, off);
                *(uint4*)(smem + AO_PB + (sr * LDP + sc0) * 2) =
                    make_uint4(pph[0], pph[1], pph[2], pph[3]);
                if ((t & 7) == 0) {
                    const float al = __expf(mo - mn);
                    m_s[sr]  = mn;
                    al_s[sr] = al;
                    l_s[sr]  = l_s[sr] * al + rs;
                }
            }
            __syncthreads();

            // ---- PV: O = alpha*O + P*V (single fp16)
            {
                const float a0 = al_s[wm * 16 + g];
                const float a1 = al_s[wm * 16 + g + 8];
                #pragma unroll
                for (int nt = 0; nt < 4; ++nt) {
                    o[nt][0] *= a0; o[nt][1] *= a0;
                    o[nt][2] *= a1; o[nt][3] *= a1;
                }
                #pragma unroll
                for (int ks = 0; ks < 4; ++ks) {
                    const int k0s = ks * 16;
                    uint32_t pa[4], vb[2][4];
                    ldsm4(pa, sb + AO_PB + 2 * (wm * 16 * LDP + k0s + aiP));
                    #pragma unroll
                    for (int h = 0; h < 2; ++h)
                        ldsm4(vb[h], sV + 2 * ((wn * 32 + h * 16) * LDV + k0s + biV));
                    #pragma unroll
                    for (int nt = 0; nt < 4; ++nt)
                        mma16816h(o[nt], pa, &vb[nt >> 1][(nt & 1) * 2]);
                }
            }
            __syncthreads();

            if (it + 2 < iters) {
                const int kn = (it + 2) * KT;
                const uint32_t k_d = sb + AO_K + st * KSTG + kr * (LDK * 2) + kq * 64;
                const uint32_t v_d = sb + AO_V + st * VSTG + vr * (LDV * 2) + vhh * 64;
                const __half* ks = gK  + (size_t)(kn + kr) * HD + kq * 32;
                const __half* vs = gVt + (size_t)vr * SEQ + kn + vhh * 32;
                #pragma unroll
                for (int j = 0; j < 4; ++j) {
                    cpa16(k_d + j * 16, ks + j * 8);
                    cpa16(v_d + j * 16, vs + j * 8);
                }
            }
            CP_COMMIT();
        }

        {
            const float li0 = 1.f / l_s[wm * 16 + g];
            const float li1 = 1.f / l_s[wm * 16 + g + 8];
            float* op0 = out + ((size_t)b * SEQ + q0 + wm * 16 + g) * HD;
            float* op1 = op0 + 8 * HD;
            #pragma unroll
            for (int nt = 0; nt < 4; ++nt) {
                const int d = wn * 32 + nt * 8 + tig * 2;
                *(float2*)(op0 + d) = make_float2(o[nt][0] * li0, o[nt][1] * li0);
                *(float2*)(op1 + d) = make_float2(o[nt][2] * li1, o[nt][3] * li1);
            }
        }
        __syncthreads();
    }
}

// ---------------------------------------------------------------------------
extern "C" void kernel_launch(void* const* d_in, const int* in_sizes, int n_in,
                              void* d_out, int out_size)
{
    const float* X  = (const float*)d_in[0];
    const float* Wq = (const float*)d_in[1];
    const float* bq = (const float*)d_in[2];
    const float* Wk = (const float*)d_in[3];
    const float* bk = (const float*)d_in[4];
    const float* Wv = (const float*)d_in[5];
    const float* bv = (const float*)d_in[6];
    float* out = (float*)d_out;

    prep_w<<<192, 256>>>(Wq, Wk, Wv);

    cudaFuncSetAttribute(qkv3, cudaFuncAttributeMaxDynamicSharedMemorySize,
                         QSM3_TOTAL);
    qkv3<<<dim3(128, 3), 256, QSM3_TOTAL>>>(X, bq, bk, bv);

    cudaFuncSetAttribute(attn7, cudaFuncAttributeMaxDynamicSharedMemorySize,
                         ASM_TOTAL);
    attn7<<<dim3(32, 4), 256, ASM_TOTAL>>>(out);
}

// round 14
// speedup vs baseline: 1.7888x; 1.3524x over previous
#include <cuda_runtime.h>
#include <cuda_fp16.h>
#include <cstdint>

#define EMBED 2048
#define HD    128
#define NB    4
#define SEQ   2048

// ---------------------------------------------------------------------------
// Scratch globals
// ---------------------------------------------------------------------------
__device__ __align__(16) __half g_Wh[3 * HD * EMBED];       // rne fp16 [w][n][k]
__device__ __align__(16) __half g_xh[(size_t)NB * SEQ * EMBED]; // rne fp16 [row][k]
__device__ __align__(16) __half g_q [NB * SEQ * HD];        // [b][s][d] fp16
__device__ __align__(16) __half g_k [NB * SEQ * HD];        // [b][s][d] fp16
__device__ __align__(16) __half g_vt[NB * HD * SEQ];        // [b][d][s] fp16

__device__ __forceinline__ uint32_t pk2h(__half a, __half b) {
    return ((uint32_t)__half_as_ushort(b) << 16) | __half_as_ushort(a);
}
__device__ __forceinline__ uint32_t smem_u32(const void* p) {
    uint32_t a;
    asm("{ .reg .u64 t; cvta.to.shared.u64 t, %1; cvt.u32.u64 %0, t; }"
        : "=r"(a) : "l"(p));
    return a;
}
// fp16 m16n8k16
__device__ __forceinline__ void mma16816h(float* c, const uint32_t* a,
                                          const uint32_t* b) {
    asm volatile(
        "mma.sync.aligned.m16n8k16.row.col.f32.f16.f16.f32 "
        "{%0,%1,%2,%3}, {%4,%5,%6,%7}, {%8,%9}, {%0,%1,%2,%3};"
        : "+f"(c[0]), "+f"(c[1]), "+f"(c[2]), "+f"(c[3])
        : "r"(a[0]), "r"(a[1]), "r"(a[2]), "r"(a[3]), "r"(b[0]), "r"(b[1]));
}
__device__ __forceinline__ void ldsm4(uint32_t* r, uint32_t saddr) {
    asm volatile("ldmatrix.sync.aligned.m8n8.x4.shared.b16 {%0,%1,%2,%3}, [%4];"
                 : "=r"(r[0]), "=r"(r[1]), "=r"(r[2]), "=r"(r[3]) : "r"(saddr));
}
__device__ __forceinline__ void cpa16(uint32_t dst, const void* src) {
    asm volatile("cp.async.cg.shared.global [%0], [%1], 16;"
                 :: "r"(dst), "l"(__cvta_generic_to_global(src)) : "memory");
}
#define CP_COMMIT() asm volatile("cp.async.commit_group;" ::: "memory")
#define CP_WAIT1()  asm volatile("cp.async.wait_group 1;" ::: "memory")

// ---------------------------------------------------------------------------
// prep_w: W fp32 [k][n] -> rne fp16 [w][n][k].  grid = 192.
// ---------------------------------------------------------------------------
__global__ __launch_bounds__(256)
void prep_w(const float* __restrict__ Wq, const float* __restrict__ Wk,
            const float* __restrict__ Wv)
{
    __shared__ float Ws[32][132];
    const int t = threadIdx.x;
    const int w  = blockIdx.x >> 6;
    const int k0 = (blockIdx.x & 63) * 32;
    const float* __restrict__ W = (w == 0) ? Wq : (w == 1 ? Wk : Wv);

    #pragma unroll
    for (int l = 0; l < 16; ++l) {
        int idx = t + l * 256;
        int kk = idx >> 7, n = idx & 127;
        Ws[kk][n] = W[(size_t)(k0 + kk) * HD + n];
    }
    __syncthreads();

    const int n = t >> 1, kh = (t & 1) * 16;
    __half* dst = g_Wh + (size_t)w * HD * EMBED + (size_t)n * EMBED + k0 + kh;
    #pragma unroll
    for (int g = 0; g < 2; ++g) {
        uint32_t hp[4];
        #pragma unroll
        for (int e = 0; e < 4; ++e)
            hp[e] = pk2h(__float2half(Ws[kh + g * 8 + e * 2][n]),
                         __float2half(Ws[kh + g * 8 + e * 2 + 1][n]));
        *(uint4*)(dst + g * 8) = make_uint4(hp[0], hp[1], hp[2], hp[3]);
    }
}

// ---------------------------------------------------------------------------
// prep_x: X fp32 -> rne fp16. grid = 512.
// ---------------------------------------------------------------------------
__global__ __launch_bounds__(256)
void prep_x(const float* __restrict__ X)
{
    const size_t N8 = (size_t)NB * SEQ * EMBED / 8;   // 2,097,152
    const size_t nthr = 512 * 256;
    for (size_t c = (size_t)blockIdx.x * 256 + threadIdx.x; c < N8; c += nthr) {
        float4 v0 = *(const float4*)(X + c * 8);
        float4 v1 = *(const float4*)(X + c * 8 + 4);
        uint4 o;
        o.x = pk2h(__float2half(v0.x), __float2half(v0.y));
        o.y = pk2h(__float2half(v0.z), __float2half(v0.w));
        o.z = pk2h(__float2half(v1.x), __float2half(v1.y));
        o.w = pk2h(__float2half(v1.z), __float2half(v1.w));
        *(uint4*)(g_xh + c * 8) = o;
    }
}

// ---------------------------------------------------------------------------
// qkv6: single-term FP16 GEMM. M64 x N128 x K2048, grid (128, 3), 3 CTAs/SM.
// Both operands fp16 via cp.async double buffer, KC=32 (2 k16 steps).
// 16 MMA per warp-iter (half of tf32 version). Epilogue -> single fp16.
// ---------------------------------------------------------------------------
#define KC    32
#define LDB   40                       // halves per row (32 + 8 pad) = 80 B
#define A6STG (64 * LDB * 2)           // 5120 B
#define B6STG (128 * LDB * 2)          // 10240 B
#define O6_A  0
#define O6_B  (2 * A6STG)              // 10240
#define O6_BIAS 34048                  // after epilogue Ct overlay (33792)
#define QSM6_TOTAL (O6_BIAS + 512)     // 34560

__global__ __launch_bounds__(256, 3)
void qkv6(const float* __restrict__ bq, const float* __restrict__ bk,
          const float* __restrict__ bv)
{
    extern __shared__ char smem[];
    const uint32_t sb = smem_u32(smem);
    float* biasS = (float*)(smem + O6_BIAS);

    const int wsel = blockIdx.y;
    const int m0   = blockIdx.x * 64;
    const int t    = threadIdx.x;
    const int wid  = t >> 5, lane = t & 31;
    const int g    = lane >> 2, tig = lane & 3;
    const int wm   = wid >> 2, wn = wid & 3;      // 2 x 4 warps -> 32x32 tiles

    const int aiA = (((lane >> 3) & 1) * 8 + (lane & 7)) * LDB + (lane >> 4) * 8;
    const int biB = ((lane >> 4) * 8 + (lane & 7)) * LDB + ((lane >> 3) & 1) * 8;

    if (t < 128) {
        const float* bias = (wsel == 0) ? bq : (wsel == 1 ? bk : bv);
        biasS[t] = bias[t];
    }

    const __half* Wh = g_Wh + (size_t)wsel * HD * EMBED;
    const int ar = t >> 2, aq = t & 3;    // A: row 0..63, 16B quarter
    const int br = t >> 1, bhh = t & 1;   // B: row 0..127, 32B half

    float c[2][4][4];
    #pragma unroll
    for (int i = 0; i < 2; ++i)
        #pragma unroll
        for (int j = 0; j < 4; ++j)
            #pragma unroll
            for (int q = 0; q < 4; ++q) c[i][j][q] = 0.f;

    #pragma unroll
    for (int pi = 0; pi < 2; ++pi) {
        const int kb = pi * KC;
        cpa16(sb + O6_A + pi * A6STG + ar * (LDB * 2) + aq * 16,
              g_xh + (size_t)(m0 + ar) * EMBED + kb + aq * 8);
        {
            const __half* src = Wh + (size_t)br * EMBED + kb + bhh * 16;
            const uint32_t dst = sb + O6_B + pi * B6STG + br * (LDB * 2) + bhh * 32;
            cpa16(dst, src);
            cpa16(dst + 16, src + 8);
        }
        CP_COMMIT();
    }

    for (int kt = 0; kt < EMBED / KC; ++kt) {
        const int st = kt & 1;
        const uint32_t sA = sb + O6_A + st * A6STG;
        const uint32_t sB = sb + O6_B + st * B6STG;

        CP_WAIT1();
        __syncthreads();

        #pragma unroll
        for (int ks = 0; ks < 2; ++ks) {
            const int ko = ks * 16;
            uint32_t a[2][4], bb[2][4];
            #pragma unroll
            for (int mi = 0; mi < 2; ++mi)
                ldsm4(a[mi], sA + 2 * ((wm * 32 + mi * 16) * LDB + ko + aiA));
            #pragma unroll
            for (int h = 0; h < 2; ++h)
                ldsm4(bb[h], sB + 2 * ((wn * 32 + h * 16) * LDB + ko + biB));
            #pragma unroll
            for (int mi = 0; mi < 2; ++mi)
                #pragma unroll
                for (int nt = 0; nt < 4; ++nt)
                    mma16816h(c[mi][nt], a[mi], &bb[nt >> 1][(nt & 1) * 2]);
        }
        __syncthreads();

        if (kt + 2 < EMBED / KC) {
            const int kb = (kt + 2) * KC;
            cpa16(sb + O6_A + st * A6STG + ar * (LDB * 2) + aq * 16,
                  g_xh + (size_t)(m0 + ar) * EMBED + kb + aq * 8);
            {
                const __half* src = Wh + (size_t)br * EMBED + kb + bhh * 16;
                const uint32_t dst = sb + O6_B + st * B6STG + br * (LDB * 2) + bhh * 32;
                cpa16(dst, src);
                cpa16(dst + 16, src + 8);
            }
        }
        CP_COMMIT();
    }

    // ---- epilogue: frags (+bias) -> Ct -> single fp16 gmem
    __syncthreads();
    float (*Ct)[132] = (float (*)[132])smem;
    #pragma unroll
    for (int mi = 0; mi < 2; ++mi) {
        const int r = wm * 32 + mi * 16 + g;
        #pragma unroll
        for (int nt = 0; nt < 4; ++nt) {
            const int n = wn * 32 + nt * 8 + tig * 2;
            Ct[r][n]         = c[mi][nt][0] + biasS[n];
            Ct[r][n + 1]     = c[mi][nt][1] + biasS[n + 1];
            Ct[r + 8][n]     = c[mi][nt][2] + biasS[n];
            Ct[r + 8][n + 1] = c[mi][nt][3] + biasS[n + 1];
        }
    }
    __syncthreads();

    const int batch = m0 >> 11, s0 = m0 & 2047;
    if (wsel < 2) {
        const int r = t >> 2, dq = (t & 3) * 32;
        __half* dst = (wsel == 0 ? g_q : g_k)
            + ((size_t)batch * SEQ + s0 + r) * HD + dq;
        #pragma unroll
        for (int qq = 0; qq < 4; ++qq) {
            uint32_t hp[4];
            #pragma unroll
            for (int e = 0; e < 4; ++e)
                hp[e] = pk2h(__float2half(Ct[r][dq + qq * 8 + e * 2]),
                             __float2half(Ct[r][dq + qq * 8 + e * 2 + 1]));
            *(uint4*)(dst + qq * 8) = make_uint4(hp[0], hp[1], hp[2], hp[3]);
        }
    } else {
        const int d = t >> 1, sch = (t & 1) * 32;
        __half* dst = g_vt + ((size_t)batch * HD + d) * SEQ + s0 + sch;
        #pragma unroll
        for (int qq = 0; qq < 4; ++qq) {
            uint32_t hp[4];
            #pragma unroll
            for (int e = 0; e < 4; ++e)
                hp[e] = pk2h(__float2half(Ct[sch + qq * 8 + e * 2][d]),
                             __float2half(Ct[sch + qq * 8 + e * 2 + 1][d]));
            *(uint4*)(dst + qq * 8) = make_uint4(hp[0], hp[1], hp[2], hp[3]);
        }
    }
}

// ---------------------------------------------------------------------------
// attn7 (unchanged, passing): all-single-fp16 flash attention, KT=64,
// cp.async 2-stage, balanced causal pairing. grid (32, 4).
// ---------------------------------------------------------------------------
#define KT   64
#define LDK  136
#define LDV  72
#define LDP  72
#define SPS  68
#define KSTG (KT * LDK * 2)
#define VSTG (HD * LDV * 2)

#define AO_Q    0
#define AO_K    (AO_Q + 32 * LDK * 2)
#define AO_V    (AO_K + 2 * KSTG)
#define AO_PS   (AO_V + 2 * VSTG)
#define AO_PB   (AO_PS + 32 * SPS * 4)
#define AO_MLA  (AO_PB + 32 * LDP * 2)
#define ASM_TOTAL (AO_MLA + 3 * 32 * 4)

__global__ __launch_bounds__(256)
void attn7(float* __restrict__ out)
{
    extern __shared__ char smem[];
    const uint32_t sb = smem_u32(smem);
    float* Ps   = (float*)(smem + AO_PS);
    float* m_s  = (float*)(smem + AO_MLA);
    float* l_s  = m_s + 32;
    float* al_s = l_s + 32;

    const int b = blockIdx.y, t = threadIdx.x;
    const int wid = t >> 5, lane = t & 31;
    const int g = lane >> 2, tig = lane & 3;
    const int wm = wid & 1, wn = wid >> 1;

    const int aiQ = (((lane >> 3) & 1) * 8 + (lane & 7)) * LDK + (lane >> 4) * 8;
    const int biK = ((lane >> 4) * 8 + (lane & 7)) * LDK + ((lane >> 3) & 1) * 8;
    const int aiP = (((lane >> 3) & 1) * 8 + (lane & 7)) * LDP + (lane >> 4) * 8;
    const int biV = ((lane >> 4) * 8 + (lane & 7)) * LDV + ((lane >> 3) & 1) * 8;

    const __half* gQ  = g_q  + (size_t)b * SEQ * HD;
    const __half* gK  = g_k  + (size_t)b * SEQ * HD;
    const __half* gVt = g_vt + (size_t)b * HD * SEQ;

    const float RSC = 0.08838834764831845f;
    const int sr = t >> 3, sc0 = (t & 7) * 8;
    const int kr = t >> 2, kq = t & 3;
    const int vr = t >> 1, vhh = t & 1;

    for (int subt = 0; subt < 2; ++subt) {
        const int jt = subt ? (63 - blockIdx.x) : blockIdx.x;
        const int q0 = jt * 32;
        const int iters = (jt >> 1) + 1;

        {
            const int r = t >> 3, dq = (t & 7) * 16;
            const __half* sh = gQ + (size_t)(q0 + r) * HD + dq;
            *(uint4*)(smem + AO_Q + (r * LDK + dq) * 2)     = *(const uint4*)sh;
            *(uint4*)(smem + AO_Q + (r * LDK + dq + 8) * 2) = *(const uint4*)(sh + 8);
        }
        if (t < 32) { m_s[t] = -1e30f; l_s[t] = 0.f; }

        float o[4][4];
        #pragma unroll
        for (int nt = 0; nt < 4; ++nt)
            #pragma unroll
            for (int q = 0; q < 4; ++q) o[nt][q] = 0.f;

        #pragma unroll
        for (int pi = 0; pi < 2; ++pi) {
            if (pi < iters) {
                const int k0 = pi * KT;
                const uint32_t k_d = sb + AO_K + pi * KSTG + kr * (LDK * 2) + kq * 64;
                const uint32_t v_d = sb + AO_V + pi * VSTG + vr * (LDV * 2) + vhh * 64;
                const __half* ks = gK  + (size_t)(k0 + kr) * HD + kq * 32;
                const __half* vs = gVt + (size_t)vr * SEQ + k0 + vhh * 32;
                #pragma unroll
                for (int j = 0; j < 4; ++j) {
                    cpa16(k_d + j * 16, ks + j * 8);
                    cpa16(v_d + j * 16, vs + j * 8);
                }
            }
            CP_COMMIT();
        }

        for (int it = 0; it < iters; ++it) {
            const int k0 = it * KT;
            const int st = it & 1;
            const uint32_t sK = sb + AO_K + st * KSTG;
            const uint32_t sV = sb + AO_V + st * VSTG;

            CP_WAIT1();
            __syncthreads();

            float s4[2][4];
            #pragma unroll
            for (int nt = 0; nt < 2; ++nt)
                #pragma unroll
                for (int q = 0; q < 4; ++q) s4[nt][q] = 0.f;
            #pragma unroll
            for (int ks = 0; ks < 8; ++ks) {
                const int k0s = ks * 16;
                uint32_t qa[4], kk[4];
                ldsm4(qa, sb + AO_Q + 2 * (wm * 16 * LDK + k0s + aiQ));
                ldsm4(kk, sK + 2 * (wn * 16 * LDK + k0s + biK));
                #pragma unroll
                for (int nt = 0; nt < 2; ++nt)
                    mma16816h(s4[nt], qa, &kk[nt * 2]);
            }
            {
                const int row0 = wm * 16 + g;
                #pragma unroll
                for (int nt = 0; nt < 2; ++nt) {
                    const int col = wn * 16 + nt * 8 + tig * 2;
                    *(float2*)&Ps[row0 * SPS + col] = make_float2(s4[nt][0], s4[nt][1]);
                    *(float2*)&Ps[(row0 + 8) * SPS + col] = make_float2(s4[nt][2], s4[nt][3]);
                }
            }
            __syncthreads();

            {
                const int gq = q0 + sr;
                float sv[8];
                float rm = -1e30f;
                #pragma unroll
                for (int j = 0; j < 8; ++j) {
                    float v = Ps[sr * SPS + sc0 + j] * RSC;
                    if (k0 + sc0 + j > gq) v = -1e10f;
                    sv[j] = v;
                    rm = fmaxf(rm, v);
                }
                #pragma unroll
                for (int off = 4; off >= 1; off >>= 1)
                    rm = fmaxf(rm, __shfl_xor_sync(0xffffffffu, rm, off));
                const float mo = m_s[sr];
                const float mn = fmaxf(mo, rm);
                float rs = 0.f;
                uint32_t pph[4];
                #pragma unroll
                for (int j = 0; j < 4; ++j) {
                    float p0 = __expf(sv[2 * j] - mn);
                    float p1 = __expf(sv[2 * j + 1] - mn);
                    rs += p0 + p1;
                    pph[j] = pk2h(__float2half(p0), __float2half(p1));
                }
                #pragma unroll
                for (int off = 4; off >= 1; off >>= 1)
                    rs += __shfl_xor_sync(0xffffffffu, rs, off);
                *(uint4*)(smem + AO_PB + (sr * LDP + sc0) * 2) =
                    make_uint4(pph[0], pph[1], pph[2], pph[3]);
                if ((t & 7) == 0) {
                    const float al = __expf(mo - mn);
                    m_s[sr]  = mn;
                    al_s[sr] = al;
                    l_s[sr]  = l_s[sr] * al + rs;
                }
            }
            __syncthreads();

            {
                const float a0 = al_s[wm * 16 + g];
                const float a1 = al_s[wm * 16 + g + 8];
                #pragma unroll
                for (int nt = 0; nt < 4; ++nt) {
                    o[nt][0] *= a0; o[nt][1] *= a0;
                    o[nt][2] *= a1; o[nt][3] *= a1;
                }
                #pragma unroll
                for (int ks = 0; ks < 4; ++ks) {
                    const int k0s = ks * 16;
                    uint32_t pa[4], vb[2][4];
                    ldsm4(pa, sb + AO_PB + 2 * (wm * 16 * LDP + k0s + aiP));
                    #pragma unroll
                    for (int h = 0; h < 2; ++h)
                        ldsm4(vb[h], sV + 2 * ((wn * 32 + h * 16) * LDV + k0s + biV));
                    #pragma unroll
                    for (int nt = 0; nt < 4; ++nt)
                        mma16816h(o[nt], pa, &vb[nt >> 1][(nt & 1) * 2]);
                }
            }
            __syncthreads();

            if (it + 2 < iters) {
                const int kn = (it + 2) * KT;
                const uint32_t k_d = sb + AO_K + st * KSTG + kr * (LDK * 2) + kq * 64;
                const uint32_t v_d = sb + AO_V + st * VSTG + vr * (LDV * 2) + vhh * 64;
                const __half* ks = gK  + (size_t)(kn + kr) * HD + kq * 32;
                const __half* vs = gVt + (size_t)vr * SEQ + kn + vhh * 32;
                #pragma unroll
                for (int j = 0; j < 4; ++j) {
                    cpa16(k_d + j * 16, ks + j * 8);
                    cpa16(v_d + j * 16, vs + j * 8);
                }
            }
            CP_COMMIT();
        }

        {
            const float li0 = 1.f / l_s[wm * 16 + g];
            const float li1 = 1.f / l_s[wm * 16 + g + 8];
            float* op0 = out + ((size_t)b * SEQ + q0 + wm * 16 + g) * HD;
            float* op1 = op0 + 8 * HD;
            #pragma unroll
            for (int nt = 0; nt < 4; ++nt) {
                const int d = wn * 32 + nt * 8 + tig * 2;
                *(float2*)(op0 + d) = make_float2(o[nt][0] * li0, o[nt][1] * li0);
                *(float2*)(op1 + d) = make_float2(o[nt][2] * li1, o[nt][3] * li1);
            }
        }
        __syncthreads();
    }
}

// ---------------------------------------------------------------------------
extern "C" void kernel_launch(void* const* d_in, const int* in_sizes, int n_in,
                              void* d_out, int out_size)
{
    const float* X  = (const float*)d_in[0];
    const float* Wq = (const float*)d_in[1];
    const float* bq = (const float*)d_in[2];
    const float* Wk = (const float*)d_in[3];
    const float* bk = (const float*)d_in[4];
    const float* Wv = (const float*)d_in[5];
    const float* bv = (const float*)d_in[6];
    float* out = (float*)d_out;

    prep_w<<<192, 256>>>(Wq, Wk, Wv);
    prep_x<<<512, 256>>>(X);

    cudaFuncSetAttribute(qkv6, cudaFuncAttributeMaxDynamicSharedMemorySize,
                         QSM6_TOTAL);
    qkv6<<<dim3(128, 3), 256, QSM6_TOTAL>>>(bq, bk, bv);

    cudaFuncSetAttribute(attn7, cudaFuncAttributeMaxDynamicSharedMemorySize,
                         ASM_TOTAL);
    attn7<<<dim3(32, 4), 256, ASM_TOTAL>>>(out);
}